// round 2
// baseline (speedup 1.0000x reference)
#include <cuda_runtime.h>
#include <math.h>

#define N    8192
#define FIN  256
#define FOUT 128

#define MT   64     // rows per block in attention kernel
#define KT   32     // j-chunk
#define WPAD 68     // padded row stride for w tile (bank-conflict relief, 16B aligned)

// ---- scratch (device globals; no allocation allowed) ----
__device__ float g_Wh[(size_t)N * FOUT];   // 4 MB
__device__ float g_s1[N], g_s2[N];
__device__ float g_R1p[N], g_R1n[N], g_E2p[N], g_E2n[N];
__device__ float g_S1M, g_S2M;

// ============================================================
// Kernel 1: Wh = h @ W^T   (h:[N,FIN], W:[FOUT,FIN] both k-major)
// block = 128 threads (one per output column f), 32 rows per block
// ============================================================
__global__ void __launch_bounds__(128) k_wh(const float* __restrict__ h,
                                            const float* __restrict__ W) {
    __shared__ float hs[32][FIN];
    const int row0 = blockIdx.x * 32;
    const int t = threadIdx.x;

    // load 32x256 h tile (coalesced float4)
    const float4* h4 = (const float4*)(h + (size_t)row0 * FIN);
    float4* hs4 = (float4*)&hs[0][0];
    #pragma unroll
    for (int u = 0; u < 16; u++) hs4[t + u * 128] = h4[t + u * 128];
    __syncthreads();

    const int f = t;
    const float4* W4 = (const float4*)(W + (size_t)f * FIN);

    float acc[32];
    #pragma unroll
    for (int r = 0; r < 32; r++) acc[r] = 0.f;

    for (int k0 = 0; k0 < FIN; k0 += 32) {
        float4 wv[8];
        #pragma unroll
        for (int c = 0; c < 8; c++) wv[c] = W4[k0 / 4 + c];
        #pragma unroll
        for (int r = 0; r < 32; r++) {
            const float4* hv4 = (const float4*)&hs[r][k0];
            #pragma unroll
            for (int c = 0; c < 8; c++) {
                float4 hv = hv4[c];
                acc[r] += hv.x * wv[c].x;
                acc[r] += hv.y * wv[c].y;
                acc[r] += hv.z * wv[c].z;
                acc[r] += hv.w * wv[c].w;
            }
        }
    }
    #pragma unroll
    for (int r = 0; r < 32; r++)
        g_Wh[(size_t)(row0 + r) * FOUT + f] = acc[r];
}

// ============================================================
// Kernel 2: s1 = Wh@a1, s2 = Wh@a2   (warp per row)
// ============================================================
__global__ void __launch_bounds__(256) k_s12(const float* __restrict__ a1,
                                             const float* __restrict__ a2) {
    const int gwarp = (blockIdx.x * 256 + threadIdx.x) >> 5;
    const int lane = threadIdx.x & 31;
    if (gwarp >= N) return;
    const float* whr = g_Wh + (size_t)gwarp * FOUT;
    float p1 = 0.f, p2 = 0.f;
    #pragma unroll
    for (int c = 0; c < 4; c++) {
        float v = whr[lane + 32 * c];
        p1 += v * __ldg(&a1[lane + 32 * c]);
        p2 += v * __ldg(&a2[lane + 32 * c]);
    }
    #pragma unroll
    for (int o = 16; o > 0; o >>= 1) {
        p1 += __shfl_xor_sync(0xffffffffu, p1, o);
        p2 += __shfl_xor_sync(0xffffffffu, p2, o);
    }
    if (lane == 0) { g_s1[gwarp] = p1; g_s2[gwarp] = p2; }
}

// ============================================================
// Kernel 2b: global maxima of s1, s2 (single block)
// ============================================================
__global__ void __launch_bounds__(256) k_max() {
    __shared__ float sm1[256], sm2[256];
    const int t = threadIdx.x;
    float m1 = -1e30f, m2 = -1e30f;
    for (int i = t; i < N; i += 256) {
        m1 = fmaxf(m1, g_s1[i]);
        m2 = fmaxf(m2, g_s2[i]);
    }
    sm1[t] = m1; sm2[t] = m2;
    __syncthreads();
    for (int s = 128; s > 0; s >>= 1) {
        if (t < s) {
            sm1[t] = fmaxf(sm1[t], sm1[t + s]);
            sm2[t] = fmaxf(sm2[t], sm2[t + s]);
        }
        __syncthreads();
    }
    if (t == 0) { g_S1M = sm1[0]; g_S2M = sm2[0]; }
}

// ============================================================
// Kernel 2c: factorized exp weights
//  exp(lrelu(s1+s2) - C1 - C2) = R1p[i]*E2p[j]  (s1+s2>=0)
//                              = R1n[i]*E2n[j]  (s1+s2< 0)
// ============================================================
__global__ void __launch_bounds__(256) k_factors() {
    const int i = blockIdx.x * 256 + threadIdx.x;
    if (i >= N) return;
    const float C1 = g_S1M, C2 = g_S2M;
    const float s1 = g_s1[i], s2 = g_s2[i];
    g_R1p[i] = expf(s1 - C1);
    g_R1n[i] = expf(0.2f * s1 - C1);
    g_E2p[i] = expf(s2 - C2);
    g_E2n[i] = expf(0.2f * s2 - C2);
}

// ============================================================
// Kernel 3: fused masked-softmax attention GEMM + ELU epilogue
//  out[i,f] = elu( (sum_j w_ij * Wh[j,f]) / (sum_j w_ij) )
//  w_ij = adj_ij>0 ? (s1_i+s2_j>=0 ? R1p_i*E2p_j : R1n_i*E2n_j) : 0
// grid = N/MT blocks, 256 threads, 8x4 register tile, prefetch pipeline
// ============================================================
__global__ void __launch_bounds__(256) k_attn(const int* __restrict__ adj,
                                              float* __restrict__ out) {
    __shared__ float w_s[KT][WPAD];     // w tile, transposed [k][m]
    __shared__ float wh_s[KT][FOUT];    // Wh tile [k][f]
    __shared__ float z_s[MT];

    const int t = threadIdx.x;
    const int row0 = blockIdx.x * MT;

    // generation-phase mapping: row m = t/4, 8 j's per thread (jg = t&3)
    const int m  = t >> 2;
    const int jg = t & 3;
    const float s1m  = g_s1[row0 + m];
    const float r1pm = g_R1p[row0 + m];
    const float r1nm = g_R1n[row0 + m];
    const size_t arow = (size_t)(row0 + m) * N;

    // FMA-phase mapping: 8 rows x 4 cols per thread
    const int cg = t & 31, rg = t >> 5;
    const int f0 = cg * 4, r0 = rg * 8;

    float acc[8][4];
    #pragma unroll
    for (int i = 0; i < 8; i++)
        #pragma unroll
        for (int j = 0; j < 4; j++) acc[i][j] = 0.f;
    float zpart = 0.f;

    // prefetch registers
    int4 aj0, aj1;
    float4 s2a, s2b, epa, epb, ena, enb;
    float4 whv[4];

    auto load_stage = [&](int j0) {
        const int jb = j0 + jg * 8;
        const int* ap = adj + arow + jb;
        aj0 = *(const int4*)ap;
        aj1 = *(const int4*)(ap + 4);
        s2a = *(const float4*)(g_s2 + jb);  s2b = *(const float4*)(g_s2 + jb + 4);
        epa = *(const float4*)(g_E2p + jb); epb = *(const float4*)(g_E2p + jb + 4);
        ena = *(const float4*)(g_E2n + jb); enb = *(const float4*)(g_E2n + jb + 4);
        #pragma unroll
        for (int u = 0; u < 4; u++) {
            const int idx = t + u * 256;
            const int kk = idx >> 5, fq = idx & 31;
            whv[u] = *(const float4*)(g_Wh + (size_t)(j0 + kk) * FOUT + fq * 4);
        }
    };

    load_stage(0);

    for (int j0 = 0; j0 < N; j0 += KT) {
        __syncthreads();   // previous FMA phase done reading smem

        // commit Wh tile
        #pragma unroll
        for (int u = 0; u < 4; u++) {
            const int idx = t + u * 256;
            const int kk = idx >> 5, fq = idx & 31;
            *(float4*)&wh_s[kk][fq * 4] = whv[u];
        }
        // compute + commit w tile, accumulate partial Z
        {
            float w;
            #define DOW(q, A, S, EP, EN)                                        \
                w = 0.f;                                                        \
                if ((A) > 0) w = (s1m + (S) >= 0.f) ? r1pm * (EP) : r1nm * (EN);\
                w_s[jg * 8 + (q)][m] = w;                                       \
                zpart += w;
            DOW(0, aj0.x, s2a.x, epa.x, ena.x)
            DOW(1, aj0.y, s2a.y, epa.y, ena.y)
            DOW(2, aj0.z, s2a.z, epa.z, ena.z)
            DOW(3, aj0.w, s2a.w, epa.w, ena.w)
            DOW(4, aj1.x, s2b.x, epb.x, enb.x)
            DOW(5, aj1.y, s2b.y, epb.y, enb.y)
            DOW(6, aj1.z, s2b.z, epb.z, enb.z)
            DOW(7, aj1.w, s2b.w, epb.w, enb.w)
            #undef DOW
        }
        // prefetch next chunk (overlaps with FMA phase)
        const int jn = j0 + KT;
        if (jn < N) load_stage(jn);

        __syncthreads();

        // FMA phase: 32 k-steps, 8x4 per thread
        #pragma unroll
        for (int kk = 0; kk < KT; kk++) {
            const float4 wa = *(const float4*)&w_s[kk][r0];       // broadcast
            const float4 wb = *(const float4*)&w_s[kk][r0 + 4];   // broadcast
            const float4 bv = *(const float4*)&wh_s[kk][f0];
            const float wr[8] = {wa.x, wa.y, wa.z, wa.w, wb.x, wb.y, wb.z, wb.w};
            const float bb[4] = {bv.x, bv.y, bv.z, bv.w};
            #pragma unroll
            for (int rr = 0; rr < 8; rr++)
                #pragma unroll
                for (int cc = 0; cc < 4; cc++)
                    acc[rr][cc] += wr[rr] * bb[cc];
        }
    }

    // reduce Z across the 4 threads sharing a row (lane bits 0,1)
    zpart += __shfl_xor_sync(0xffffffffu, zpart, 1);
    zpart += __shfl_xor_sync(0xffffffffu, zpart, 2);
    if (jg == 0) z_s[m] = zpart;
    __syncthreads();

    // epilogue: divide by Z, ELU, store
    #pragma unroll
    for (int rr = 0; rr < 8; rr++) {
        const float inv = 1.0f / z_s[r0 + rr];
        float4 o;
        float v;
        v = acc[rr][0] * inv; o.x = v > 0.f ? v : expm1f(v);
        v = acc[rr][1] * inv; o.y = v > 0.f ? v : expm1f(v);
        v = acc[rr][2] * inv; o.z = v > 0.f ? v : expm1f(v);
        v = acc[rr][3] * inv; o.w = v > 0.f ? v : expm1f(v);
        *(float4*)(out + (size_t)(row0 + r0 + rr) * FOUT + f0) = o;
    }
}

// ============================================================
extern "C" void kernel_launch(void* const* d_in, const int* in_sizes, int n_in,
                              void* d_out, int out_size) {
    const float* h   = (const float*)d_in[0];
    const int*   adj = (const int*)d_in[1];
    const float* W   = (const float*)d_in[2];
    const float* a1  = (const float*)d_in[3];
    const float* a2  = (const float*)d_in[4];
    float* out = (float*)d_out;

    k_wh     <<<N / 32, 128>>>(h, W);
    k_s12    <<<N / 8, 256>>>(a1, a2);
    k_max    <<<1, 256>>>();
    k_factors<<<N / 256, 256>>>();
    k_attn   <<<N / MT, 256>>>(adj, out);
}

// round 4
// speedup vs baseline: 2.9384x; 2.9384x over previous
#include <cuda_runtime.h>
#include <cuda_fp16.h>
#include <stdint.h>
#include <math.h>

#define N      8192
#define FIN    256
#define FOUT   128
#define MT     128
#define KC     64
#define KSLICE 4096
#define NC     64           // chunks per CTA (KSLICE/KC)

// smem layout (bytes)
#define OFF_S2   0
#define OFF_EP   16384
#define OFF_EN   32768
#define ADJ_STG  34816      // 128*68*4
#define OFF_ADJ  49152
#define B_STG    18432      // 128*72*2
#define OFF_B    (OFF_ADJ + 3 * ADJ_STG)          // 153600
#define OFF_A    (OFF_B + 3 * B_STG)              // 208896
#define SMEM_TOTAL (OFF_A + B_STG)                // 227328

__device__ float g_Wh[(size_t)N * FOUT];
__device__ __half g_WhT[(size_t)FOUT * N];        // transposed fp16
__device__ float g_s1[N], g_s2[N];
__device__ float g_R1p[N], g_R1n[N], g_E2p[N], g_E2n[N];
__device__ float g_s2max;
__device__ float g_part[2][(size_t)N * FOUT];
__device__ float g_Zpart[2][N];

__device__ __forceinline__ uint32_t smem_u32(const void* p) {
    uint32_t a;
    asm("{ .reg .u64 t; cvta.to.shared.u64 t, %1; cvt.u32.u64 %0, t; }" : "=r"(a) : "l"(p));
    return a;
}
__device__ __forceinline__ void cpa16(uint32_t s, const void* g) {
    asm volatile("cp.async.cg.shared.global [%0], [%1], 16;" :: "r"(s), "l"(g));
}
#define CP_COMMIT() asm volatile("cp.async.commit_group;" ::: "memory")
#define CP_WAIT1()  asm volatile("cp.async.wait_group 1;" ::: "memory")

__device__ __forceinline__ void ldsm4(uint32_t* r, uint32_t addr) {
    asm volatile("ldmatrix.sync.aligned.m8n8.x4.shared.b16 {%0,%1,%2,%3}, [%4];"
        : "=r"(r[0]), "=r"(r[1]), "=r"(r[2]), "=r"(r[3]) : "r"(addr));
}
__device__ __forceinline__ void mma16816(float* d, const uint32_t* a, const uint32_t* b) {
    asm volatile("mma.sync.aligned.m16n8k16.row.col.f32.f16.f16.f32 "
        "{%0,%1,%2,%3}, {%4,%5,%6,%7}, {%8,%9}, {%0,%1,%2,%3};"
        : "+f"(d[0]), "+f"(d[1]), "+f"(d[2]), "+f"(d[3])
        : "r"(a[0]), "r"(a[1]), "r"(a[2]), "r"(a[3]), "r"(b[0]), "r"(b[1]));
}

// ---- Wh = h @ W^T (fp32) + transposed fp16 copy ----
__global__ void __launch_bounds__(128) k_wh(const float* __restrict__ h,
                                            const float* __restrict__ W) {
    __shared__ float hs[32][FIN];
    const int row0 = blockIdx.x * 32, t = threadIdx.x;
    const float4* h4 = (const float4*)(h + (size_t)row0 * FIN);
    float4* hs4 = (float4*)&hs[0][0];
    #pragma unroll
    for (int u = 0; u < 16; u++) hs4[t + u * 128] = h4[t + u * 128];
    __syncthreads();
    const float4* W4 = (const float4*)(W + (size_t)t * FIN);
    float acc[32];
    #pragma unroll
    for (int r = 0; r < 32; r++) acc[r] = 0.f;
    for (int k0 = 0; k0 < FIN; k0 += 32) {
        float4 wv[8];
        #pragma unroll
        for (int c = 0; c < 8; c++) wv[c] = W4[k0 / 4 + c];
        #pragma unroll
        for (int r = 0; r < 32; r++) {
            const float4* hv4 = (const float4*)&hs[r][k0];
            #pragma unroll
            for (int c = 0; c < 8; c++) {
                float4 hv = hv4[c];
                acc[r] += hv.x * wv[c].x; acc[r] += hv.y * wv[c].y;
                acc[r] += hv.z * wv[c].z; acc[r] += hv.w * wv[c].w;
            }
        }
    }
    #pragma unroll
    for (int r = 0; r < 32; r++) {
        g_Wh[(size_t)(row0 + r) * FOUT + t] = acc[r];
        g_WhT[(size_t)t * N + row0 + r] = __float2half_rn(acc[r]);
    }
}

__global__ void __launch_bounds__(256) k_s12(const float* __restrict__ a1,
                                             const float* __restrict__ a2) {
    const int gw = (blockIdx.x * 256 + threadIdx.x) >> 5, lane = threadIdx.x & 31;
    const float* whr = g_Wh + (size_t)gw * FOUT;
    float p1 = 0.f, p2 = 0.f;
    #pragma unroll
    for (int c = 0; c < 4; c++) {
        float v = whr[lane + 32 * c];
        p1 += v * __ldg(&a1[lane + 32 * c]);
        p2 += v * __ldg(&a2[lane + 32 * c]);
    }
    #pragma unroll
    for (int o = 16; o > 0; o >>= 1) {
        p1 += __shfl_xor_sync(~0u, p1, o); p2 += __shfl_xor_sync(~0u, p2, o);
    }
    if (lane == 0) { g_s1[gw] = p1; g_s2[gw] = p2; }
}

__global__ void __launch_bounds__(1024) k_s2max() {
    __shared__ float red[1024];
    const int t = threadIdx.x;
    float m = -1e30f;
    for (int i = t; i < N; i += 1024) m = fmaxf(m, g_s2[i]);
    red[t] = m; __syncthreads();
    for (int s = 512; s > 0; s >>= 1) {
        if (t < s) red[t] = fmaxf(red[t], red[t + s]);
        __syncthreads();
    }
    if (t == 0) g_s2max = red[0];
}

// per-row shift: c_i = lrelu(s1_i + s2max) - ln(1024) -> row max weight = 1024 (fp16-safe)
__global__ void __launch_bounds__(256) k_factors() {
    const int i = blockIdx.x * 256 + threadIdx.x;
    const float s1 = g_s1[i], s2 = g_s2[i];
    const float tt = s1 + g_s2max;
    const float c = (tt > 0.f ? tt : 0.2f * tt) - 6.9314718f;
    g_R1p[i] = expf(s1 - c);
    g_R1n[i] = expf(0.2f * s1 - c);
    g_E2p[i] = expf(s2);
    g_E2n[i] = expf(0.2f * s2);
}

// ---- fused masked-softmax attention GEMM on HMMA (mma.sync fp16) ----
__global__ void __launch_bounds__(256, 1) k_attn(const int* __restrict__ adj) {
    extern __shared__ char smem[];
    const uint32_t sb = smem_u32(smem);
    const int t = threadIdx.x, wid = t >> 5, lane = t & 31;
    const int mt_ = blockIdx.x >> 1, slice = blockIdx.x & 1;
    const int row0 = mt_ * MT, jbase = slice * KSLICE;

    // cp.async fill helpers
    auto fill_adj = [&](int c, int s) {
        const size_t gcol = (size_t)jbase + (size_t)c * KC;
        #pragma unroll
        for (int k = 0; k < 8; k++) {
            const int id = t + k * 256;           // 2048 chunks of 16B
            const int r = id >> 4, cc = id & 15;
            cpa16(sb + OFF_ADJ + s * ADJ_STG + r * 272 + cc * 16,
                  adj + (size_t)(row0 + r) * N + gcol + cc * 4);
        }
    };
    auto fill_B = [&](int c, int s) {
        const size_t gcol = (size_t)jbase + (size_t)c * KC;
        #pragma unroll
        for (int k = 0; k < 4; k++) {
            const int id = t + k * 256;           // 1024 chunks
            const int f = id >> 3, cc = id & 7;
            cpa16(sb + OFF_B + s * B_STG + f * 144 + cc * 16,
                  g_WhT + (size_t)f * N + gcol + cc * 8);
        }
    };

    // prologue: factors (whole slice) + stages 0,1
    {
        const float* srcs[3] = { g_s2 + jbase, g_E2p + jbase, g_E2n + jbase };
        #pragma unroll
        for (int a = 0; a < 3; a++)
            #pragma unroll
            for (int k = 0; k < 4; k++) {
                const int ch = t + k * 256;
                cpa16(sb + OFF_S2 + a * 16384 + ch * 16, srcs[a] + ch * 4);
            }
        fill_adj(0, 0); fill_B(0, 0); CP_COMMIT();
        fill_adj(1, 1); fill_B(1, 1); CP_COMMIT();
    }

    // gen mapping
    const int m = t >> 1, jh = (t & 1) * 32;
    const int row = row0 + m;
    const float thr = -g_s1[row];
    const float r1p = g_R1p[row], r1n = g_R1n[row];
    float zacc = 0.f;

    // mma mapping: 8 warps = 4x2; warp tile 32 rows x 64 cols
    const int r0 = (wid >> 1) * 32, c0 = (wid & 1) * 64;
    float acc[2][8][4];
    #pragma unroll
    for (int i = 0; i < 2; i++)
        #pragma unroll
        for (int j = 0; j < 8; j++)
            #pragma unroll
            for (int q = 0; q < 4; q++) acc[i][j][q] = 0.f;

    const uint32_t aBase = sb + OFF_A + (r0 + (lane & 15)) * 144 + (lane >> 4) * 16;
    const uint32_t bOffW = (uint32_t)((c0 + (lane & 7) + ((lane >> 4) & 1) * 8) * 144
                                      + ((lane >> 3) & 1) * 16);

    for (int c = 0; c < NC; c++) {
        const int s = c % 3;
        CP_WAIT1();
        __syncthreads();

        // ---- gen: 32 w's per thread into sA ----
        {
            const int4* ar = (const int4*)(smem + OFF_ADJ + s * ADJ_STG + m * 272 + jh * 4);
            const float4* s2p = (const float4*)(smem + OFF_S2 + (c * KC + jh) * 4);
            const float4* epp = (const float4*)(smem + OFF_EP + (c * KC + jh) * 4);
            const float4* enp = (const float4*)(smem + OFF_EN + (c * KC + jh) * 4);
            uint32_t v[16];
            #pragma unroll
            for (int u = 0; u < 8; u++) {
                const int4 a4 = ar[u];
                const float4 sv = s2p[u], ep = epp[u], en = enp[u];
                float w0 = (sv.x >= thr) ? r1p * ep.x : r1n * en.x; if (a4.x == 0) w0 = 0.f;
                float w1 = (sv.y >= thr) ? r1p * ep.y : r1n * en.y; if (a4.y == 0) w1 = 0.f;
                float w2 = (sv.z >= thr) ? r1p * ep.z : r1n * en.z; if (a4.z == 0) w2 = 0.f;
                float w3 = (sv.w >= thr) ? r1p * ep.w : r1n * en.w; if (a4.w == 0) w3 = 0.f;
                zacc += (w0 + w1) + (w2 + w3);
                __half2 p0 = __floats2half2_rn(w0, w1), p1 = __floats2half2_rn(w2, w3);
                v[2 * u] = *(uint32_t*)&p0; v[2 * u + 1] = *(uint32_t*)&p1;
            }
            uint4* dst = (uint4*)(smem + OFF_A + m * 144 + jh * 2);
            dst[0] = make_uint4(v[0], v[1], v[2], v[3]);
            dst[1] = make_uint4(v[4], v[5], v[6], v[7]);
            dst[2] = make_uint4(v[8], v[9], v[10], v[11]);
            dst[3] = make_uint4(v[12], v[13], v[14], v[15]);
        }
        __syncthreads();

        // prefetch stage c+2 (overwrites stage read at iter c-1; all threads past it)
        if (c + 2 < NC) { fill_adj(c + 2, (c + 2) % 3); fill_B(c + 2, (c + 2) % 3); }
        CP_COMMIT();

        // ---- mma: 4 k-steps of 16 ----
        const uint32_t bBase = sb + OFF_B + s * B_STG + bOffW;
        #pragma unroll
        for (int kk = 0; kk < 4; kk++) {
            uint32_t a[2][4], b[4][4];
            ldsm4(a[0], aBase + kk * 32);
            ldsm4(a[1], aBase + 16 * 144 + kk * 32);
            #pragma unroll
            for (int ng = 0; ng < 4; ng++)
                ldsm4(b[ng], bBase + ng * 16 * 144 + kk * 32);
            #pragma unroll
            for (int mi = 0; mi < 2; mi++)
                #pragma unroll
                for (int nt = 0; nt < 8; nt++)
                    mma16816(acc[mi][nt], a[mi], &b[nt >> 1][(nt & 1) * 2]);
        }
    }

    // Z reduce (threads t, t^1 share row)
    zacc += __shfl_xor_sync(~0u, zacc, 1);
    if ((t & 1) == 0) g_Zpart[slice][row] = zacc;

    // epilogue: write accumulators to g_part
    {
        const int quad = lane >> 2, qc = (lane & 3) * 2;
        #pragma unroll
        for (int mi = 0; mi < 2; mi++)
            #pragma unroll
            for (int nt = 0; nt < 8; nt++) {
                const int rg = row0 + r0 + mi * 16 + quad;
                const int col = c0 + nt * 8 + qc;
                float* p = g_part[slice] + (size_t)rg * FOUT + col;
                *(float2*)p = make_float2(acc[mi][nt][0], acc[mi][nt][1]);
                *(float2*)(p + 8 * FOUT) = make_float2(acc[mi][nt][2], acc[mi][nt][3]);
            }
    }
}

// combine K-slices: out = elu((p0+p1)/(z0+z1))
__global__ void __launch_bounds__(256) k_final(float* __restrict__ out) {
    const int idx = blockIdx.x * 256 + threadIdx.x;   // quad index
    const int row = idx >> 5, c4 = (idx & 31) * 4;
    const float4 p0 = *(const float4*)(g_part[0] + (size_t)row * FOUT + c4);
    const float4 p1 = *(const float4*)(g_part[1] + (size_t)row * FOUT + c4);
    const float inv = 1.0f / (g_Zpart[0][row] + g_Zpart[1][row]);
    float4 o; float v;
    v = (p0.x + p1.x) * inv; o.x = v > 0.f ? v : expm1f(v);
    v = (p0.y + p1.y) * inv; o.y = v > 0.f ? v : expm1f(v);
    v = (p0.z + p1.z) * inv; o.z = v > 0.f ? v : expm1f(v);
    v = (p0.w + p1.w) * inv; o.w = v > 0.f ? v : expm1f(v);
    *(float4*)(out + (size_t)row * FOUT + c4) = o;
}

extern "C" void kernel_launch(void* const* d_in, const int* in_sizes, int n_in,
                              void* d_out, int out_size) {
    const float* h   = (const float*)d_in[0];
    const int*   adj = (const int*)d_in[1];
    const float* W   = (const float*)d_in[2];
    const float* a1  = (const float*)d_in[3];
    const float* a2  = (const float*)d_in[4];
    float* out = (float*)d_out;

    cudaFuncSetAttribute(k_attn, cudaFuncAttributeMaxDynamicSharedMemorySize, SMEM_TOTAL);

    k_wh     <<<N / 32, 128>>>(h, W);
    k_s12    <<<N / 8, 256>>>(a1, a2);
    k_s2max  <<<1, 1024>>>();
    k_factors<<<N / 256, 256>>>();
    k_attn   <<<128, 256, SMEM_TOTAL>>>(adj);
    k_final  <<<N * FOUT / 1024, 256>>>(out);
}